// round 11
// baseline (speedup 1.0000x reference)
#include <cuda_runtime.h>
#include <math.h>

typedef unsigned long long ull;

#define LAT 123
#define DIMA 128
#define HID 256
#define NT 50
#define NSTEP 49
#define NTHR 384            // 12 warps * 4 rows = 48 rows
#define MROW 48
#define NBLK 128            // 6144/48, single wave

// smem (ull units): yin[48][128] dup | act[48][128] j2-packed -> 96 KB (L1 keeps ~132 KB for weights)
#define ACT_OFF 6144
#define SMEM_ULL 12288
#define SMEM_BYTES (SMEM_ULL*8)   // 98304 B

// packed weights (+1 chunk pad = 256 ull so distance-1 prefetch never faults)
__device__ ull g_w1jp[DIMA*128 + 256];   // [d][j2] = (W1[2j2][d], W1[2j2+1][d])
__device__ ull g_w2jp[128*DIMA + 256];   // [j2][d] = (W2[d][2j2], W2[d][2j2+1])
__device__ ull g_b1p[128];               // (b1[2j2], b1[2j2+1])

__device__ __forceinline__ ull pk2(float lo, float hi){
  ull r; asm("mov.b64 %0, {%1, %2};" : "=l"(r) : "f"(lo), "f"(hi)); return r;
}
__device__ __forceinline__ void upk2(ull v, float &lo, float &hi){
  asm("mov.b64 {%0, %1}, %2;" : "=f"(lo), "=f"(hi) : "l"(v));
}
__device__ __forceinline__ ull fma2_(ull a, ull b, ull c){
  ull d; asm("fma.rn.f32x2 %0, %1, %2, %3;" : "=l"(d) : "l"(a), "l"(b), "l"(c)); return d;
}
__device__ __forceinline__ ull add2_(ull a, ull b){
  ull d; asm("add.rn.f32x2 %0, %1, %2;" : "=l"(d) : "l"(a), "l"(b)); return d;
}

__device__ __forceinline__ float fast_tanh(float x){
  float ax = fabsf(x);
  float e = __expf(-2.0f * ax);
  float r = __fdividef(1.0f - e, 1.0f + e);
  return copysignf(r, x);
}
__device__ __forceinline__ ull tanh2p(ull v){
  float lo, hi; upk2(v, lo, hi);
  return pk2(fast_tanh(lo), fast_tanh(hi));
}

__global__ void pack_kernel(const float* __restrict__ W1, const float* __restrict__ W2,
                            const float* __restrict__ b1){
  int i = blockIdx.x*256 + threadIdx.x;      // 0..16383
  int d  = i >> 7, j2 = i & 127;
  g_w1jp[i] = pk2(W1[(2*j2)*DIMA + d], W1[(2*j2+1)*DIMA + d]);
  int j2b = i >> 7, d2 = i & 127;
  g_w2jp[i] = pk2(W2[d2*HID + 2*j2b], W2[d2*HID + 2*j2b+1]);
  if (i < 128) g_b1p[i] = pk2(b1[2*i], b1[2*i+1]);
  if (i < 256){            // zero the prefetch pads (any finite value is fine)
    g_w1jp[DIMA*128 + i] = 0ull;
    g_w2jp[128*DIMA + i] = 0ull;
  }
}

__global__ __launch_bounds__(NTHR,1)
void ode_kernel(const float* __restrict__ fp, const float* __restrict__ ts,
                const float* __restrict__ b2, float* __restrict__ out)
{
  extern __shared__ ull sm[];
  ull* yin = sm;                       // [r][d]  dup(y[r][d]), stride 128
  ull* act = sm + ACT_OFF;             // [r][j2] packed (tanh_{2j2}, tanh_{2j2+1})

  const int tid = threadIdx.x;
  const int lg  = tid & 31;
  const int wp  = tid >> 5;            // warp 0..11; warp owns rows r0..r0+3 end-to-end
  const int r0  = wp*4;
  const int grow = blockIdx.x*MROW + r0;

  const int jA = 2*lg, jB = 64 + 2*lg;   // P1 j2 pair-bases (thread owns j2 in {jA,jA+1,jB,jB+1})
  const int dA = 2*lg, dB = 64 + 2*lg;   // P2 d bases

  const ull b1A0 = g_b1p[jA], b1A1 = g_b1p[jA+1];
  const ull b1B0 = g_b1p[jB], b1B1 = g_b1p[jB+1];
  const float b2v[4] = { __ldg(b2+dA), __ldg(b2+dA+1), __ldg(b2+dB), __ldg(b2+dB+1) };

  // ---- init: y0 = [first_point | 0], write yin-dup + out[t=0] ----
  float y0r[4][4], k1r[4][4], k2r[4][4];
  #pragma unroll
  for (int rr=0; rr<4; ++rr){
    int g = grow + rr;
    const float* fr = fp + (size_t)g*LAT;
    float v0 = (dA   < LAT) ? __ldg(fr+dA)   : 0.0f;
    float v1 = (dA+1 < LAT) ? __ldg(fr+dA+1) : 0.0f;
    float v2 = (dB   < LAT) ? __ldg(fr+dB)   : 0.0f;
    float v3 = (dB+1 < LAT) ? __ldg(fr+dB+1) : 0.0f;
    y0r[0][rr]=v0; y0r[1][rr]=v1; y0r[2][rr]=v2; y0r[3][rr]=v3;
    ulonglong2 s0; s0.x = pk2(v0,v0); s0.y = pk2(v1,v1);
    ulonglong2 s1; s1.x = pk2(v2,v2); s1.y = pk2(v3,v3);
    *(ulonglong2*)&yin[(r0+rr)*128 + dA] = s0;
    *(ulonglong2*)&yin[(r0+rr)*128 + dB] = s1;
    *(float2*)(out + ((size_t)g*NT)*DIMA + dA) = make_float2(v0,v1);
    *(float2*)(out + ((size_t)g*NT)*DIMA + dB) = make_float2(v2,v3);
  }
  __syncthreads();

  #pragma unroll 1
  for (int step=0; step<NSTEP; ++step){
    const float t0 = __ldg(ts+step);
    const float h  = __ldg(ts+step+1) - t0;

    #pragma unroll 1
    for (int st=0; st<4; ++st){
      // ========= P1: act[r][j2] = tanh(b1 + sum_d W1[j][d]*y[r][d]) =========
      ull acc[4][4];
      #pragma unroll
      for (int i=0;i<4;i++)
        #pragma unroll
        for (int rr=0;rr<4;rr++) acc[i][rr]=0ull;

      {
        const ull* nb = g_w1jp;
        const ull* yb = &yin[r0*128];
        // distance-1 prefetch: w holds chunk cc, n holds chunk cc+1
        ulonglong2 w0=__ldg((const ulonglong2*)(nb+jA));
        ulonglong2 w1=__ldg((const ulonglong2*)(nb+jB));
        ulonglong2 w2=__ldg((const ulonglong2*)(nb+128+jA));
        ulonglong2 w3=__ldg((const ulonglong2*)(nb+128+jB));
        #pragma unroll 1
        for (int cc=0; cc<64; ++cc){
          nb += 256;
          ulonglong2 n0=__ldg((const ulonglong2*)(nb+jA));
          ulonglong2 n1=__ldg((const ulonglong2*)(nb+jB));
          ulonglong2 n2=__ldg((const ulonglong2*)(nb+128+jA));
          ulonglong2 n3=__ldg((const ulonglong2*)(nb+128+jB));
          #pragma unroll
          for (int rr=0; rr<4; ++rr){
            ulonglong2 yv = *(const ulonglong2*)(yb + rr*128 + 2*cc);  // broadcast, 1 wf
            acc[0][rr]=fma2_(w0.x, yv.x, acc[0][rr]);
            acc[1][rr]=fma2_(w0.y, yv.x, acc[1][rr]);
            acc[2][rr]=fma2_(w1.x, yv.x, acc[2][rr]);
            acc[3][rr]=fma2_(w1.y, yv.x, acc[3][rr]);
            acc[0][rr]=fma2_(w2.x, yv.y, acc[0][rr]);
            acc[1][rr]=fma2_(w2.y, yv.y, acc[1][rr]);
            acc[2][rr]=fma2_(w3.x, yv.y, acc[2][rr]);
            acc[3][rr]=fma2_(w3.y, yv.y, acc[3][rr]);
          }
          w0=n0; w1=n1; w2=n2; w3=n3;
        }
      }
      #pragma unroll
      for (int rr=0; rr<4; ++rr){
        ulonglong2 sA, sB;
        sA.x = tanh2p(add2_(acc[0][rr], b1A0));
        sA.y = tanh2p(add2_(acc[1][rr], b1A1));
        sB.x = tanh2p(add2_(acc[2][rr], b1B0));
        sB.y = tanh2p(add2_(acc[3][rr], b1B1));
        *(ulonglong2*)&act[(r0+rr)*128 + jA] = sA;
        *(ulonglong2*)&act[(r0+rr)*128 + jB] = sB;
      }
      __syncthreads();   // converge warps on the W2 stream (L1 reuse)

      // ========= P2: k[r][d] = b2 + sum_j W2[d][j]*act[r][j] =========
      ull a2[4][4];
      #pragma unroll
      for (int i=0;i<4;i++)
        #pragma unroll
        for (int rr=0;rr<4;rr++) a2[i][rr]=0ull;

      {
        const ull* nb = g_w2jp;
        const ull* ab = &act[r0*128];
        ulonglong2 w0=__ldg((const ulonglong2*)(nb+dA));
        ulonglong2 w1=__ldg((const ulonglong2*)(nb+dB));
        ulonglong2 w2=__ldg((const ulonglong2*)(nb+128+dA));
        ulonglong2 w3=__ldg((const ulonglong2*)(nb+128+dB));
        #pragma unroll 1
        for (int cc=0; cc<64; ++cc){
          nb += 256;
          ulonglong2 n0=__ldg((const ulonglong2*)(nb+dA));
          ulonglong2 n1=__ldg((const ulonglong2*)(nb+dB));
          ulonglong2 n2=__ldg((const ulonglong2*)(nb+128+dA));
          ulonglong2 n3=__ldg((const ulonglong2*)(nb+128+dB));
          #pragma unroll
          for (int rr=0; rr<4; ++rr){
            ulonglong2 av = *(const ulonglong2*)(ab + rr*128 + 2*cc);  // broadcast, 1 wf
            a2[0][rr]=fma2_(w0.x, av.x, a2[0][rr]);
            a2[1][rr]=fma2_(w0.y, av.x, a2[1][rr]);
            a2[2][rr]=fma2_(w1.x, av.x, a2[2][rr]);
            a2[3][rr]=fma2_(w1.y, av.x, a2[3][rr]);
            a2[0][rr]=fma2_(w2.x, av.y, a2[0][rr]);
            a2[1][rr]=fma2_(w2.y, av.y, a2[1][rr]);
            a2[2][rr]=fma2_(w3.x, av.y, a2[2][rr]);
            a2[3][rr]=fma2_(w3.y, av.y, a2[3][rr]);
          }
          w0=n0; w1=n1; w2=n2; w3=n3;
        }
      }
      // horizontal add + bias -> k
      float kk[4][4];
      #pragma unroll
      for (int i=0;i<4;i++)
        #pragma unroll
        for (int rr=0;rr<4;rr++){
          float lo, hi; upk2(a2[i][rr], lo, hi);
          kk[i][rr] = lo + hi + b2v[i];
        }

      // ========= RK4(3/8) stage update (all state in registers) =========
      #pragma unroll
      for (int rr=0; rr<4; ++rr){
        float yn[4];
        if (st == 0){
          const float c = h*(1.0f/3.0f);
          #pragma unroll
          for (int i=0;i<4;i++){
            k1r[i][rr] = kk[i][rr];
            yn[i] = fmaf(c, kk[i][rr], y0r[i][rr]);
          }
        } else if (st == 1){
          const float c = -h*(1.0f/3.0f);
          #pragma unroll
          for (int i=0;i<4;i++){
            k2r[i][rr] = kk[i][rr];
            yn[i] = fmaf(c, k1r[i][rr], fmaf(h, kk[i][rr], y0r[i][rr]));
          }
        } else if (st == 2){
          #pragma unroll
          for (int i=0;i<4;i++){
            yn[i] = fmaf(h, k1r[i][rr] - k2r[i][rr] + kk[i][rr], y0r[i][rr]);
            // fold Butcher sum: A = k1 + 3*(k2 + k3) into k2 slot
            k2r[i][rr] = fmaf(3.0f, k2r[i][rr] + kk[i][rr], k1r[i][rr]);
          }
        } else {
          const float c = h*0.125f;
          #pragma unroll
          for (int i=0;i<4;i++){
            yn[i] = fmaf(c, k2r[i][rr] + kk[i][rr], y0r[i][rr]);   // y + h/8*(A + k4)
            y0r[i][rr] = yn[i];
          }
          int g = grow + rr;
          *(float2*)(out + ((size_t)g*NT + step+1)*DIMA + dA) = make_float2(yn[0], yn[1]);
          *(float2*)(out + ((size_t)g*NT + step+1)*DIMA + dB) = make_float2(yn[2], yn[3]);
        }
        ulonglong2 w0; w0.x = pk2(yn[0],yn[0]); w0.y = pk2(yn[1],yn[1]);
        ulonglong2 w1; w1.x = pk2(yn[2],yn[2]); w1.y = pk2(yn[3],yn[3]);
        *(ulonglong2*)&yin[(r0+rr)*128 + dA] = w0;
        *(ulonglong2*)&yin[(r0+rr)*128 + dB] = w1;
      }
      __syncthreads();   // converge before next stage's W1 stream
    }
  }
}

extern "C" void kernel_launch(void* const* d_in, const int* in_sizes, int n_in,
                              void* d_out, int out_size)
{
  const float* fp = (const float*)d_in[0];   // (3,2048,123)
  const float* ts = (const float*)d_in[1];   // (50)
  const float* W1 = (const float*)d_in[2];   // (256,128)
  const float* b1 = (const float*)d_in[3];   // (256)
  const float* W2 = (const float*)d_in[4];   // (128,256)
  const float* b2 = (const float*)d_in[5];   // (128)
  float* out = (float*)d_out;                // (3,2048,50,128)

  pack_kernel<<<64, 256>>>(W1, W2, b1);

  cudaFuncSetAttribute(ode_kernel,
                       cudaFuncAttributeMaxDynamicSharedMemorySize, SMEM_BYTES);
  ode_kernel<<<NBLK, NTHR, SMEM_BYTES>>>(fp, ts, b2, out);
}

// round 12
// speedup vs baseline: 1.0049x; 1.0049x over previous
#include <cuda_runtime.h>
#include <math.h>

typedef unsigned long long ull;

#define LAT 123
#define DIMA 128
#define HID 256
#define NT 50
#define NSTEP 49
#define NTHR 384            // 12 warps = 6 row-groups x 2 feature-slices
#define MROW 48
#define NBLK 128            // 6144/48, single wave

// smem (ull units): yin[48][128] dup | act[48][128] j2-packed  -> 96 KB
#define ACT_OFF 6144
#define SMEM_ULL 12288
#define SMEM_BYTES (SMEM_ULL*8)   // 98304 B

// packed weights; +1024 ull pad so distance-2 prefetch never faults
__device__ ull g_w1jp[DIMA*128 + 1024];   // [d][j2] = (W1[2j2][d], W1[2j2+1][d])
__device__ ull g_w2jp[128*DIMA + 1024];   // [j2][d] = (W2[d][2j2], W2[d][2j2+1])
__device__ ull g_b1p[128];                // (b1[2j2], b1[2j2+1])

__device__ __forceinline__ ull pk2(float lo, float hi){
  ull r; asm("mov.b64 %0, {%1, %2};" : "=l"(r) : "f"(lo), "f"(hi)); return r;
}
__device__ __forceinline__ void upk2(ull v, float &lo, float &hi){
  asm("mov.b64 {%0, %1}, %2;" : "=f"(lo), "=f"(hi) : "l"(v));
}
__device__ __forceinline__ ull fma2_(ull a, ull b, ull c){
  ull d; asm("fma.rn.f32x2 %0, %1, %2, %3;" : "=l"(d) : "l"(a), "l"(b), "l"(c)); return d;
}
__device__ __forceinline__ ull add2_(ull a, ull b){
  ull d; asm("add.rn.f32x2 %0, %1, %2;" : "=l"(d) : "l"(a), "l"(b)); return d;
}

__device__ __forceinline__ float fast_tanh(float x){
  float ax = fabsf(x);
  float e = __expf(-2.0f * ax);
  float r = __fdividef(1.0f - e, 1.0f + e);
  return copysignf(r, x);
}
__device__ __forceinline__ ull tanh2p(ull v){
  float lo, hi; upk2(v, lo, hi);
  return pk2(fast_tanh(lo), fast_tanh(hi));
}

__global__ void pack_kernel(const float* __restrict__ W1, const float* __restrict__ W2,
                            const float* __restrict__ b1){
  int i = blockIdx.x*256 + threadIdx.x;      // 0..16383
  int d  = i >> 7, j2 = i & 127;
  g_w1jp[i] = pk2(W1[(2*j2)*DIMA + d], W1[(2*j2+1)*DIMA + d]);
  int j2b = i >> 7, d2 = i & 127;
  g_w2jp[i] = pk2(W2[d2*HID + 2*j2b], W2[d2*HID + 2*j2b+1]);
  if (i < 128) g_b1p[i] = pk2(b1[2*i], b1[2*i+1]);
  if (i < 1024){
    g_w1jp[DIMA*128 + i] = 0ull;
    g_w2jp[128*DIMA + i] = 0ull;
  }
}

__global__ __launch_bounds__(NTHR,1)
void ode_kernel(const float* __restrict__ fp, const float* __restrict__ ts,
                const float* __restrict__ b2, float* __restrict__ out)
{
  extern __shared__ ull sm[];
  ull* yin = sm;                       // [r][d]  dup(y[r][d]), stride 128
  ull* act = sm + ACT_OFF;             // [r][j2] packed (tanh_{2j2}, tanh_{2j2+1})

  const int tid = threadIdx.x;
  const int lg  = tid & 31;
  const int wp  = tid >> 5;            // 0..11
  const int sh  = wp & 1;              // feature-slice half (j2-half in P1, d-half in P2)
  const int rg  = wp >> 1;             // row-group 0..5; warp owns 8 rows
  const int r0  = rg*8;
  const int grow = blockIdx.x*MROW + r0;

  const int jj = 64*sh + 2*lg;         // P1: lane owns j2 = jj, jj+1
  const int dd = 64*sh + 2*lg;         // P2/RK4: lane owns d = dd, dd+1

  const ull b1A = g_b1p[jj], b1B = g_b1p[jj+1];
  const float b2a = __ldg(b2+dd), b2b = __ldg(b2+dd+1);

  // ---- init: y0 = [first_point | 0], write yin-dup + out[t=0] ----
  float y0r[2][8], k1r[2][8], kAr[2][8];
  #pragma unroll
  for (int r=0; r<8; ++r){
    int g = grow + r;
    const float* fr = fp + (size_t)g*LAT;
    float v0 = (dd   < LAT) ? __ldg(fr+dd)   : 0.0f;
    float v1 = (dd+1 < LAT) ? __ldg(fr+dd+1) : 0.0f;
    y0r[0][r]=v0; y0r[1][r]=v1;
    ulonglong2 s; s.x = pk2(v0,v0); s.y = pk2(v1,v1);
    *(ulonglong2*)&yin[(r0+r)*128 + dd] = s;
    *(float2*)(out + ((size_t)g*NT)*DIMA + dd) = make_float2(v0,v1);
  }
  __syncthreads();

  #pragma unroll 1
  for (int step=0; step<NSTEP; ++step){
    const float t0 = __ldg(ts+step);
    const float h  = __ldg(ts+step+1) - t0;

    #pragma unroll 1
    for (int st=0; st<4; ++st){
      // ===== P1: act[r][j2] = tanh(b1 + sum_d W1[j][d]*y[r][d]); warp slice: 64 j2, 8 rows =====
      ull acc0[8], acc1[8];
      #pragma unroll
      for (int r=0;r<8;r++){ acc0[r]=0ull; acc1[r]=0ull; }
      {
        const ull* wb = g_w1jp + jj;
        const ull* yb = yin + r0*128;
        ulonglong2 A0=__ldg((const ulonglong2*)(wb));       // d=0
        ulonglong2 A1=__ldg((const ulonglong2*)(wb+128));   // d=1
        ulonglong2 B0=__ldg((const ulonglong2*)(wb+256));   // d=2
        ulonglong2 B1=__ldg((const ulonglong2*)(wb+384));   // d=3
        wb += 512;
        #pragma unroll 1
        for (int cc=0; cc<32; ++cc){               // two 2-d chunks per iter
          {
            ulonglong2 c0=A0, c1=A1;
            A0=__ldg((const ulonglong2*)(wb));
            A1=__ldg((const ulonglong2*)(wb+128));
            #pragma unroll
            for (int r=0;r<8;++r){
              ulonglong2 yv = *(const ulonglong2*)(yb + r*128 + 4*cc);   // broadcast
              acc0[r]=fma2_(c0.x, yv.x, acc0[r]);
              acc1[r]=fma2_(c0.y, yv.x, acc1[r]);
              acc0[r]=fma2_(c1.x, yv.y, acc0[r]);
              acc1[r]=fma2_(c1.y, yv.y, acc1[r]);
            }
          }
          {
            ulonglong2 c0=B0, c1=B1;
            B0=__ldg((const ulonglong2*)(wb+256));
            B1=__ldg((const ulonglong2*)(wb+384));
            #pragma unroll
            for (int r=0;r<8;++r){
              ulonglong2 yv = *(const ulonglong2*)(yb + r*128 + 4*cc + 2);
              acc0[r]=fma2_(c0.x, yv.x, acc0[r]);
              acc1[r]=fma2_(c0.y, yv.x, acc1[r]);
              acc0[r]=fma2_(c1.x, yv.y, acc0[r]);
              acc1[r]=fma2_(c1.y, yv.y, acc1[r]);
            }
          }
          wb += 512;
        }
      }
      #pragma unroll
      for (int r=0;r<8;++r){
        ulonglong2 s;
        s.x = tanh2p(add2_(acc0[r], b1A));
        s.y = tanh2p(add2_(acc1[r], b1B));
        *(ulonglong2*)&act[(r0+r)*128 + jj] = s;
      }
      __syncthreads();

      // ===== P2: k[r][d] = b2 + sum_j W2[d][j]*act[r][j]; warp slice: 64 d, 8 rows =====
      ull a20[8], a21[8];
      #pragma unroll
      for (int r=0;r<8;r++){ a20[r]=0ull; a21[r]=0ull; }
      {
        const ull* wb = g_w2jp + dd;
        const ull* ab = act + r0*128;
        ulonglong2 A0=__ldg((const ulonglong2*)(wb));       // j2=0
        ulonglong2 A1=__ldg((const ulonglong2*)(wb+128));   // j2=1
        ulonglong2 B0=__ldg((const ulonglong2*)(wb+256));
        ulonglong2 B1=__ldg((const ulonglong2*)(wb+384));
        wb += 512;
        #pragma unroll 1
        for (int cc=0; cc<32; ++cc){
          {
            ulonglong2 c0=A0, c1=A1;
            A0=__ldg((const ulonglong2*)(wb));
            A1=__ldg((const ulonglong2*)(wb+128));
            #pragma unroll
            for (int r=0;r<8;++r){
              ulonglong2 av = *(const ulonglong2*)(ab + r*128 + 4*cc);   // broadcast
              a20[r]=fma2_(c0.x, av.x, a20[r]);
              a21[r]=fma2_(c0.y, av.x, a21[r]);
              a20[r]=fma2_(c1.x, av.y, a20[r]);
              a21[r]=fma2_(c1.y, av.y, a21[r]);
            }
          }
          {
            ulonglong2 c0=B0, c1=B1;
            B0=__ldg((const ulonglong2*)(wb+256));
            B1=__ldg((const ulonglong2*)(wb+384));
            #pragma unroll
            for (int r=0;r<8;++r){
              ulonglong2 av = *(const ulonglong2*)(ab + r*128 + 4*cc + 2);
              a20[r]=fma2_(c0.x, av.x, a20[r]);
              a21[r]=fma2_(c0.y, av.x, a21[r]);
              a20[r]=fma2_(c1.x, av.y, a20[r]);
              a21[r]=fma2_(c1.y, av.y, a21[r]);
            }
          }
          wb += 512;
        }
      }
      float kk0[8], kk1[8];
      #pragma unroll
      for (int r=0;r<8;++r){
        float lo, hi;
        upk2(a20[r], lo, hi); kk0[r] = lo + hi + b2a;
        upk2(a21[r], lo, hi); kk1[r] = lo + hi + b2b;
      }

      // ===== RK4(3/8) stage update (all state in registers) =====
      #pragma unroll
      for (int r=0;r<8;++r){
        float kv[2] = {kk0[r], kk1[r]};
        float yn[2];
        if (st == 0){
          const float c = h*(1.0f/3.0f);
          #pragma unroll
          for (int i=0;i<2;i++){
            k1r[i][r] = kv[i];
            yn[i] = fmaf(c, kv[i], y0r[i][r]);
          }
        } else if (st == 1){
          const float c = -h*(1.0f/3.0f);
          #pragma unroll
          for (int i=0;i<2;i++){
            kAr[i][r] = kv[i];                       // k2 parked
            yn[i] = fmaf(c, k1r[i][r], fmaf(h, kv[i], y0r[i][r]));
          }
        } else if (st == 2){
          #pragma unroll
          for (int i=0;i<2;i++){
            yn[i] = fmaf(h, k1r[i][r] - kAr[i][r] + kv[i], y0r[i][r]);
            kAr[i][r] = fmaf(3.0f, kAr[i][r] + kv[i], k1r[i][r]);  // fold k1+3(k2+k3)
          }
        } else {
          const float c = h*0.125f;
          #pragma unroll
          for (int i=0;i<2;i++){
            yn[i] = fmaf(c, kAr[i][r] + kv[i], y0r[i][r]);
            y0r[i][r] = yn[i];
          }
          int g = grow + r;
          *(float2*)(out + ((size_t)g*NT + step+1)*DIMA + dd) = make_float2(yn[0], yn[1]);
        }
        ulonglong2 s; s.x = pk2(yn[0],yn[0]); s.y = pk2(yn[1],yn[1]);
        *(ulonglong2*)&yin[(r0+r)*128 + dd] = s;
      }
      __syncthreads();
    }
  }
}

extern "C" void kernel_launch(void* const* d_in, const int* in_sizes, int n_in,
                              void* d_out, int out_size)
{
  const float* fp = (const float*)d_in[0];   // (3,2048,123)
  const float* ts = (const float*)d_in[1];   // (50)
  const float* W1 = (const float*)d_in[2];   // (256,128)
  const float* b1 = (const float*)d_in[3];   // (256)
  const float* W2 = (const float*)d_in[4];   // (128,256)
  const float* b2 = (const float*)d_in[5];   // (128)
  float* out = (float*)d_out;                // (3,2048,50,128)

  pack_kernel<<<64, 256>>>(W1, W2, b1);

  cudaFuncSetAttribute(ode_kernel,
                       cudaFuncAttributeMaxDynamicSharedMemorySize, SMEM_BYTES);
  ode_kernel<<<NBLK, NTHR, SMEM_BYTES>>>(fp, ts, b2, out);
}

// round 14
// speedup vs baseline: 1.1442x; 1.1387x over previous
#include <cuda_runtime.h>
#include <math.h>

typedef unsigned long long ull;

#define LAT 123
#define DIMA 128
#define HID 256
#define NT 50
#define NSTEP 49
#define NTHR 256
#define MROW 48
#define NBLK 128            // 6144/48, single wave

// smem layout (ull units): yin[48][128] dup | act[48][128] j2-packed | ksm 3*48*128 floats
#define ACT_OFF 6144
#define KSM_OFF 12288
#define SMEM_ULL (12288 + 9216)
#define SMEM_BYTES (SMEM_ULL*8)   // 172032 B

// packed weights (built once by pack_kernel)
__device__ ull g_w1jp[DIMA*128];   // [d][j2] = (W1[2j2][d], W1[2j2+1][d])
__device__ ull g_w2jp[128*DIMA];   // [j2][d] = (W2[d][2j2], W2[d][2j2+1])
__device__ ull g_b1p[128];         // (b1[2j2], b1[2j2+1])

__device__ __forceinline__ ull pk2(float lo, float hi){
  ull r; asm("mov.b64 %0, {%1, %2};" : "=l"(r) : "f"(lo), "f"(hi)); return r;
}
__device__ __forceinline__ void upk2(ull v, float &lo, float &hi){
  asm("mov.b64 {%0, %1}, %2;" : "=f"(lo), "=f"(hi) : "l"(v));
}
__device__ __forceinline__ ull fma2_(ull a, ull b, ull c){
  ull d; asm("fma.rn.f32x2 %0, %1, %2, %3;" : "=l"(d) : "l"(a), "l"(b), "l"(c)); return d;
}
__device__ __forceinline__ ull add2_(ull a, ull b){
  ull d; asm("add.rn.f32x2 %0, %1, %2;" : "=l"(d) : "l"(a), "l"(b)); return d;
}

// HW tanh: single MUFU op (vs 2 for exp+rcp). |err| ~5e-4 worst-case, damped by the
// integrator; final rel_err predicted ~1e-4 vs 1e-3 budget.
__device__ __forceinline__ float fast_tanh(float x){
  float r; asm("tanh.approx.f32 %0, %1;" : "=f"(r) : "f"(x)); return r;
}
__device__ __forceinline__ ull tanh2p(ull v){
  float lo, hi; upk2(v, lo, hi);
  return pk2(fast_tanh(lo), fast_tanh(hi));
}

__global__ void pack_kernel(const float* __restrict__ W1, const float* __restrict__ W2,
                            const float* __restrict__ b1){
  int i = blockIdx.x*256 + threadIdx.x;      // 0..16383
  int d  = i >> 7, j2 = i & 127;
  g_w1jp[i] = pk2(W1[(2*j2)*DIMA + d], W1[(2*j2+1)*DIMA + d]);
  int j2b = i >> 7, d2 = i & 127;
  g_w2jp[i] = pk2(W2[d2*HID + 2*j2b], W2[d2*HID + 2*j2b+1]);
  if (i < 128) g_b1p[i] = pk2(b1[2*i], b1[2*i+1]);
}

__global__ __launch_bounds__(NTHR,1)
void ode_kernel(const float* __restrict__ fp, const float* __restrict__ ts,
                const float* __restrict__ b2, float* __restrict__ out)
{
  extern __shared__ ull sm[];
  ull* yin = sm;                       // [r][d]  dup(y[r][d]), stride 128
  ull* act = sm + ACT_OFF;             // [r][j2] (tanh_{2j2}, tanh_{2j2+1}), stride 128
  float* ksm = (float*)(sm + KSM_OFF); // [s][r][d]

  const int tid = threadIdx.x;
  const int lg  = tid & 31;
  const int rg  = tid >> 5;
  const int r0  = rg*6;
  const int grow = blockIdx.x*MROW + r0;

  const int jA = 2*lg, jB = 64 + 2*lg;   // j2 pair-bases (thread owns j2 in {jA,jA+1,jB,jB+1})
  const int dA = 2*lg, dB = 64 + 2*lg;   // d bases for P2/RK4

  const ull b1A0 = g_b1p[jA], b1A1 = g_b1p[jA+1];
  const ull b1B0 = g_b1p[jB], b1B1 = g_b1p[jB+1];
  const float b2v[4] = { __ldg(b2+dA), __ldg(b2+dA+1), __ldg(b2+dB), __ldg(b2+dB+1) };

  // ---- init: y0 = [first_point | 0], write yin-dup + out[t=0] ----
  float y2[4][6];
  #pragma unroll
  for (int rr=0; rr<6; ++rr){
    int g = grow + rr;
    const float* fr = fp + (size_t)g*LAT;
    float v0 = (dA   < LAT) ? __ldg(fr+dA)   : 0.0f;
    float v1 = (dA+1 < LAT) ? __ldg(fr+dA+1) : 0.0f;
    float v2 = (dB   < LAT) ? __ldg(fr+dB)   : 0.0f;
    float v3 = (dB+1 < LAT) ? __ldg(fr+dB+1) : 0.0f;
    y2[0][rr]=v0; y2[1][rr]=v1; y2[2][rr]=v2; y2[3][rr]=v3;
    ulonglong2 s0; s0.x = pk2(v0,v0); s0.y = pk2(v1,v1);
    ulonglong2 s1; s1.x = pk2(v2,v2); s1.y = pk2(v3,v3);
    *(ulonglong2*)&yin[(r0+rr)*128 + dA] = s0;
    *(ulonglong2*)&yin[(r0+rr)*128 + dB] = s1;
    *(float2*)(out + ((size_t)g*NT)*DIMA + dA) = make_float2(v0,v1);
    *(float2*)(out + ((size_t)g*NT)*DIMA + dB) = make_float2(v2,v3);
  }
  __syncthreads();

  #pragma unroll 1
  for (int step=0; step<NSTEP; ++step){
    const float t0 = __ldg(ts+step);
    const float h  = __ldg(ts+step+1) - t0;

    #pragma unroll 1
    for (int st=0; st<4; ++st){
      // ========= P1: act[r][j2] = tanh(b1 + sum_d W1[j][d]*y[r][d]) (j-pair packed) =========
      ull acc[4][6];
      #pragma unroll
      for (int i=0;i<4;i++)
        #pragma unroll
        for (int rr=0;rr<6;rr++) acc[i][rr]=0ull;

      #pragma unroll 2
      for (int d=0; d<128; d+=2){
        const ull* w1b = g_w1jp + d*128;
        ulonglong2 wA = __ldg((const ulonglong2*)(w1b + jA));         // (j2=jA, jA+1) @ d
        ulonglong2 wB = __ldg((const ulonglong2*)(w1b + jB));
        ulonglong2 wC = __ldg((const ulonglong2*)(w1b + 128 + jA));   // @ d+1
        ulonglong2 wD = __ldg((const ulonglong2*)(w1b + 128 + jB));
        #pragma unroll
        for (int rr=0; rr<6; ++rr){
          ulonglong2 yv = *(const ulonglong2*)&yin[(r0+rr)*128 + d];  // dup y @ d, d+1 (broadcast)
          acc[0][rr]=fma2_(wA.x, yv.x, acc[0][rr]);
          acc[1][rr]=fma2_(wA.y, yv.x, acc[1][rr]);
          acc[2][rr]=fma2_(wB.x, yv.x, acc[2][rr]);
          acc[3][rr]=fma2_(wB.y, yv.x, acc[3][rr]);
          acc[0][rr]=fma2_(wC.x, yv.y, acc[0][rr]);
          acc[1][rr]=fma2_(wC.y, yv.y, acc[1][rr]);
          acc[2][rr]=fma2_(wD.x, yv.y, acc[2][rr]);
          acc[3][rr]=fma2_(wD.y, yv.y, acc[3][rr]);
        }
      }
      #pragma unroll
      for (int rr=0; rr<6; ++rr){
        ulonglong2 sA, sB;
        sA.x = tanh2p(add2_(acc[0][rr], b1A0));
        sA.y = tanh2p(add2_(acc[1][rr], b1A1));
        sB.x = tanh2p(add2_(acc[2][rr], b1B0));
        sB.y = tanh2p(add2_(acc[3][rr], b1B1));
        *(ulonglong2*)&act[(r0+rr)*128 + jA] = sA;
        *(ulonglong2*)&act[(r0+rr)*128 + jB] = sB;
      }
      __syncthreads();

      // ========= P2: k[r][d] = b2 + sum_j W2[d][j]*act[r][j]  (j-pair packed both ops) =========
      ull a2[4][6];
      #pragma unroll
      for (int i=0;i<4;i++)
        #pragma unroll
        for (int rr=0;rr<6;rr++) a2[i][rr]=0ull;

      #pragma unroll 2
      for (int j2=0; j2<128; j2+=2){
        const ull* w2b = g_w2jp + j2*128;
        ulonglong2 vA = __ldg((const ulonglong2*)(w2b + dA));         // (d=dA,dA+1) @ j2
        ulonglong2 vB = __ldg((const ulonglong2*)(w2b + dB));
        ulonglong2 vC = __ldg((const ulonglong2*)(w2b + 128 + dA));   // @ j2+1
        ulonglong2 vD = __ldg((const ulonglong2*)(w2b + 128 + dB));
        #pragma unroll
        for (int rr=0; rr<6; ++rr){
          ulonglong2 av = *(const ulonglong2*)&act[(r0+rr)*128 + j2]; // (j2, j2+1) (broadcast)
          a2[0][rr]=fma2_(vA.x, av.x, a2[0][rr]);
          a2[1][rr]=fma2_(vA.y, av.x, a2[1][rr]);
          a2[2][rr]=fma2_(vB.x, av.x, a2[2][rr]);
          a2[3][rr]=fma2_(vB.y, av.x, a2[3][rr]);
          a2[0][rr]=fma2_(vC.x, av.y, a2[0][rr]);
          a2[1][rr]=fma2_(vC.y, av.y, a2[1][rr]);
          a2[2][rr]=fma2_(vD.x, av.y, a2[2][rr]);
          a2[3][rr]=fma2_(vD.y, av.y, a2[3][rr]);
        }
      }
      // horizontal add + bias -> k
      float kk[4][6];
      #pragma unroll
      for (int i=0;i<4;i++)
        #pragma unroll
        for (int rr=0;rr<6;rr++){
          float lo, hi; upk2(a2[i][rr], lo, hi);
          kk[i][rr] = lo + hi + b2v[i];
        }

      // ========= RK4(3/8) stage update =========
      float* k0 = ksm;                 // [r][d]
      float* k1s = ksm + 6144;
      float* k2s = ksm + 12288;
      #pragma unroll
      for (int rr=0; rr<6; ++rr){
        const int ro = (r0+rr)*128;
        float yn[4];
        if (st == 0){
          *(float2*)&k0[ro+dA] = make_float2(kk[0][rr], kk[1][rr]);
          *(float2*)&k0[ro+dB] = make_float2(kk[2][rr], kk[3][rr]);
          const float c = h*(1.0f/3.0f);
          #pragma unroll
          for (int i=0;i<4;i++) yn[i] = fmaf(c, kk[i][rr], y2[i][rr]);
        } else if (st == 1){
          *(float2*)&k1s[ro+dA] = make_float2(kk[0][rr], kk[1][rr]);
          *(float2*)&k1s[ro+dB] = make_float2(kk[2][rr], kk[3][rr]);
          float2 p0 = *(float2*)&k0[ro+dA];
          float2 p1 = *(float2*)&k0[ro+dB];
          float k1v[4] = {p0.x, p0.y, p1.x, p1.y};
          const float c = -h*(1.0f/3.0f);
          #pragma unroll
          for (int i=0;i<4;i++) yn[i] = fmaf(c, k1v[i], fmaf(h, kk[i][rr], y2[i][rr]));
        } else if (st == 2){
          *(float2*)&k2s[ro+dA] = make_float2(kk[0][rr], kk[1][rr]);
          *(float2*)&k2s[ro+dB] = make_float2(kk[2][rr], kk[3][rr]);
          float2 p0 = *(float2*)&k0[ro+dA],  p1 = *(float2*)&k0[ro+dB];
          float2 q0 = *(float2*)&k1s[ro+dA], q1 = *(float2*)&k1s[ro+dB];
          float k1v[4] = {p0.x, p0.y, p1.x, p1.y};
          float k2v[4] = {q0.x, q0.y, q1.x, q1.y};
          #pragma unroll
          for (int i=0;i<4;i++) yn[i] = fmaf(h, k1v[i] - k2v[i] + kk[i][rr], y2[i][rr]);
        } else {
          float2 p0 = *(float2*)&k0[ro+dA],  p1 = *(float2*)&k0[ro+dB];
          float2 q0 = *(float2*)&k1s[ro+dA], q1 = *(float2*)&k1s[ro+dB];
          float2 s0 = *(float2*)&k2s[ro+dA], s1 = *(float2*)&k2s[ro+dB];
          float k1v[4] = {p0.x, p0.y, p1.x, p1.y};
          float k2v[4] = {q0.x, q0.y, q1.x, q1.y};
          float k3v[4] = {s0.x, s0.y, s1.x, s1.y};
          const float c = h*0.125f;
          #pragma unroll
          for (int i=0;i<4;i++){
            float sum = k1v[i] + kk[i][rr] + 3.0f*(k2v[i] + k3v[i]);
            yn[i] = fmaf(c, sum, y2[i][rr]);
            y2[i][rr] = yn[i];
          }
          int g = grow + rr;
          *(float2*)(out + ((size_t)g*NT + step+1)*DIMA + dA) = make_float2(yn[0], yn[1]);
          *(float2*)(out + ((size_t)g*NT + step+1)*DIMA + dB) = make_float2(yn[2], yn[3]);
        }
        ulonglong2 w0; w0.x = pk2(yn[0],yn[0]); w0.y = pk2(yn[1],yn[1]);
        ulonglong2 w1; w1.x = pk2(yn[2],yn[2]); w1.y = pk2(yn[3],yn[3]);
        *(ulonglong2*)&yin[ro + dA] = w0;
        *(ulonglong2*)&yin[ro + dB] = w1;
      }
      __syncthreads();
    }
  }
}

extern "C" void kernel_launch(void* const* d_in, const int* in_sizes, int n_in,
                              void* d_out, int out_size)
{
  const float* fp = (const float*)d_in[0];   // (3,2048,123)
  const float* ts = (const float*)d_in[1];   // (50)
  const float* W1 = (const float*)d_in[2];   // (256,128)
  const float* b1 = (const float*)d_in[3];   // (256)
  const float* W2 = (const float*)d_in[4];   // (128,256)
  const float* b2 = (const float*)d_in[5];   // (128)
  float* out = (float*)d_out;                // (3,2048,50,128)

  pack_kernel<<<64, 256>>>(W1, W2, b1);

  cudaFuncSetAttribute(ode_kernel,
                       cudaFuncAttributeMaxDynamicSharedMemorySize, SMEM_BYTES);
  ode_kernel<<<NBLK, NTHR, SMEM_BYTES>>>(fp, ts, b2, out);
}

// round 16
// speedup vs baseline: 4.7900x; 4.1862x over previous
#include <cuda_runtime.h>
#include <cuda_fp16.h>
#include <math.h>

typedef unsigned int u32;

#define LAT 123
#define NT 50
#define NSTEP 49
#define NTHR 256
#define NBLK 128             // 128 CTAs x 48 rows = 6144, single wave

// smem halfs strides (padded: +8 halfs = 16B -> bank = 4*row+quad, conflict-free)
#define S1 136               // k=d dimension stride (128+8)
#define S2 264               // k=j dimension stride (256+8)

#define OFF_W1 0                         // w1s[j=256][S1]  (B of P1: n=j, k=d) fp16-hi
#define OFF_W2 69632                     // w2s[d=128][S2]  (B of P2: n=d, k=j) fp16-hi
#define OFF_YH 137216                    // yh[r=48][S1]
#define OFF_YL 150272                    // yl[r=48][S1]
#define OFF_AH 163328                    // ah[r=48][S2]
#define OFF_AL 188672                    // al[r=48][S2]
#define SMEM_TOTAL 214016                // <= 232448

// lo-weights, fragment-packed for coalesced LDG:
// P1 tile t = jtile*8 + ks (jtile 0..31, ks 0..7): u32[t*64 + reg*32 + lane]
// P2 tile t = dtile*16 + ks (dtile 0..15, ks 0..15)
__device__ u32 g_w1l[16384];
__device__ u32 g_w2l[16384];

__device__ __forceinline__ float tanh_hw(float x){
  float r; asm("tanh.approx.f32 %0, %1;" : "=f"(r) : "f"(x)); return r;
}
__device__ __forceinline__ void mma16816(float* c, u32 a0,u32 a1,u32 a2,u32 a3, u32 b0,u32 b1){
  asm volatile(
    "mma.sync.aligned.m16n8k16.row.col.f32.f16.f16.f32 "
    "{%0,%1,%2,%3},{%4,%5,%6,%7},{%8,%9},{%0,%1,%2,%3};"
    : "+f"(c[0]), "+f"(c[1]), "+f"(c[2]), "+f"(c[3])
    : "r"(a0), "r"(a1), "r"(a2), "r"(a3), "r"(b0), "r"(b1));
}
__device__ __forceinline__ u32 lds32(const half* p){ return *(const u32*)p; }

__device__ __forceinline__ half lo_h(float w){
  half hh = __float2half_rn(w);
  return __float2half_rn(w - __half2float(hh));
}

// pack W-lo residuals into B-fragment order
__global__ void pack_lo(const float* __restrict__ W1, const float* __restrict__ W2){
  int idx = blockIdx.x*256 + threadIdx.x;     // 0..32767
  if (idx < 16384){
    int t = idx >> 6, rem = idx & 63;
    int reg = rem >> 5, lane = rem & 31;
    int n = (t >> 3)*8 + (lane >> 2);               // j
    int k = (t & 7)*16 + (lane & 3)*2 + reg*8;      // d
    half h0 = lo_h(W1[n*128 + k]);
    half h1 = lo_h(W1[n*128 + k + 1]);
    half2 v = __halves2half2(h0, h1);
    g_w1l[idx] = *(u32*)&v;
  } else {
    int i2 = idx - 16384;
    int t = i2 >> 6, rem = i2 & 63;
    int reg = rem >> 5, lane = rem & 31;
    int n = (t >> 4)*8 + (lane >> 2);               // d
    int k = (t & 15)*16 + (lane & 3)*2 + reg*8;     // j
    half h0 = lo_h(W2[n*256 + k]);
    half h1 = lo_h(W2[n*256 + k + 1]);
    half2 v = __halves2half2(h0, h1);
    g_w2l[i2] = *(u32*)&v;
  }
}

__global__ __launch_bounds__(NTHR,1)
void ode_kernel(const float* __restrict__ fp, const float* __restrict__ ts,
                const float* __restrict__ W1, const float* __restrict__ b1,
                const float* __restrict__ W2, const float* __restrict__ b2,
                float* __restrict__ out)
{
  extern __shared__ char smem[];
  half* w1s = (half*)(smem + OFF_W1);
  half* w2s = (half*)(smem + OFF_W2);
  half* yh  = (half*)(smem + OFF_YH);
  half* yl  = (half*)(smem + OFF_YL);
  half* ah  = (half*)(smem + OFF_AH);
  half* al  = (half*)(smem + OFF_AL);

  const int tid  = threadIdx.x;
  const int lane = tid & 31;
  const int w    = tid >> 5;          // warp 0..7
  const int rA   = lane >> 2;         // fragment row (0..7)
  const int cK   = (lane & 3) * 2;    // fragment k-pair base

  // ---- load hi-weights into smem fp16 (one-time) ----
  for (int idx = tid; idx < 256*128; idx += NTHR){
    int j = idx >> 7, d = idx & 127;
    w1s[j*S1 + d] = __float2half_rn(W1[idx]);          // W1[j][d]
  }
  for (int idx = tid; idx < 128*256; idx += NTHR){
    int d = idx >> 8, j = idx & 255;
    w2s[d*S2 + j] = __float2half_rn(W2[idx]);          // W2[d][j]
  }

  // per-thread bias regs
  float b1v[4][2], b2v[2][2];
  #pragma unroll
  for (int tn=0; tn<4; ++tn){
    int j = w*32 + tn*8 + cK;
    b1v[tn][0] = __ldg(b1 + j);
    b1v[tn][1] = __ldg(b1 + j + 1);
  }
  #pragma unroll
  for (int tn=0; tn<2; ++tn){
    int d = w*16 + tn*8 + cK;
    b2v[tn][0] = __ldg(b2 + d);
    b2v[tn][1] = __ldg(b2 + d + 1);
  }

  const int grow = blockIdx.x * 48;

  // ---- RK4 cell ownership (matches P2 C layout): r = tm*16+q*8+rA, d = w*16+tn*8+cK+p
  float ys[24], k1s[24], kAs[24];
  #pragma unroll
  for (int tm=0; tm<3; ++tm)
    #pragma unroll
    for (int q=0; q<2; ++q){
      int r = tm*16 + q*8 + rA;
      int g = grow + r;
      #pragma unroll
      for (int tn=0; tn<2; ++tn){
        int d0 = w*16 + tn*8 + cK;
        float v0 = (d0   < LAT) ? __ldg(fp + (size_t)g*LAT + d0)   : 0.0f;
        float v1 = (d0+1 < LAT) ? __ldg(fp + (size_t)g*LAT + d0+1) : 0.0f;
        ys[tm*8+q*4+tn*2+0] = v0;
        ys[tm*8+q*4+tn*2+1] = v1;
        half h0 = __float2half_rn(v0), h1 = __float2half_rn(v1);
        *(half2*)(yh + r*S1 + d0) = __halves2half2(h0, h1);
        *(half2*)(yl + r*S1 + d0) = __halves2half2(
            __float2half_rn(v0 - __half2float(h0)),
            __float2half_rn(v1 - __half2float(h1)));
        *(float2*)(out + ((size_t)g*NT)*128 + d0) = make_float2(v0, v1);
      }
    }
  __syncthreads();

  #pragma unroll 1
  for (int step=0; step<NSTEP; ++step){
    const float t0 = __ldg(ts+step);
    const float h  = __ldg(ts+step+1) - t0;

    #pragma unroll 1
    for (int st=0; st<4; ++st){
      // ===== P1: C1[r, j] = yh*W1h + yl*W1h + yh*W1l ; warp j-slice [w*32, w*32+32) =====
      float C1[3][4][4];
      #pragma unroll
      for (int tm=0;tm<3;++tm)
        #pragma unroll
        for (int tn=0;tn<4;++tn)
          #pragma unroll
          for (int c=0;c<4;++c) C1[tm][tn][c]=0.0f;

      #pragma unroll
      for (int ks=0; ks<8; ++ks){
        const int ko = ks*16 + cK;
        u32 wb[4][2], wl0[4], wl1[4];
        #pragma unroll
        for (int tn=0; tn<4; ++tn){
          const half* p = w1s + (w*32 + tn*8 + rA)*S1 + ko;
          wb[tn][0] = lds32(p);
          wb[tn][1] = lds32(p + 8);
          const u32* q = g_w1l + ((w*4+tn)*8 + ks)*64;
          wl0[tn] = __ldg(q + lane);
          wl1[tn] = __ldg(q + 32 + lane);
        }
        #pragma unroll
        for (int tm=0; tm<3; ++tm){
          const half* py = yh + (tm*16 + rA)*S1 + ko;
          u32 a0 = lds32(py),          a1 = lds32(py + 8*S1);
          u32 a2 = lds32(py + 8),      a3 = lds32(py + 8*S1 + 8);
          const half* pl = yl + (tm*16 + rA)*S1 + ko;
          u32 l0 = lds32(pl),          l1 = lds32(pl + 8*S1);
          u32 l2 = lds32(pl + 8),      l3 = lds32(pl + 8*S1 + 8);
          #pragma unroll
          for (int tn=0; tn<4; ++tn){
            mma16816(C1[tm][tn], a0,a1,a2,a3, wb[tn][0], wb[tn][1]);
            mma16816(C1[tm][tn], l0,l1,l2,l3, wb[tn][0], wb[tn][1]);
            mma16816(C1[tm][tn], a0,a1,a2,a3, wl0[tn], wl1[tn]);
          }
        }
      }

      // epilogue: act = tanh(C1 + b1), split hi/lo, store [r][j]
      #pragma unroll
      for (int tm=0; tm<3; ++tm)
        #pragma unroll
        for (int tn=0; tn<4; ++tn){
          int jb = w*32 + tn*8 + cK;
          float h0 = tanh_hw(C1[tm][tn][0] + b1v[tn][0]);
          float h1 = tanh_hw(C1[tm][tn][1] + b1v[tn][1]);
          float h2 = tanh_hw(C1[tm][tn][2] + b1v[tn][0]);
          float h3 = tanh_hw(C1[tm][tn][3] + b1v[tn][1]);
          half a0 = __float2half_rn(h0), a1 = __float2half_rn(h1);
          half a2 = __float2half_rn(h2), a3 = __float2half_rn(h3);
          int r0 = tm*16 + rA;
          *(half2*)(ah + r0*S2 + jb)       = __halves2half2(a0, a1);
          *(half2*)(ah + (r0+8)*S2 + jb)   = __halves2half2(a2, a3);
          *(half2*)(al + r0*S2 + jb)       = __halves2half2(
              __float2half_rn(h0 - __half2float(a0)),
              __float2half_rn(h1 - __half2float(a1)));
          *(half2*)(al + (r0+8)*S2 + jb)   = __halves2half2(
              __float2half_rn(h2 - __half2float(a2)),
              __float2half_rn(h3 - __half2float(a3)));
        }
      __syncthreads();

      // ===== P2: C2[r, d] = ah*W2h + al*W2h + ah*W2l ; warp d-slice [w*16, w*16+16) =====
      float C2[3][2][4];
      #pragma unroll
      for (int tm=0;tm<3;++tm)
        #pragma unroll
        for (int tn=0;tn<2;++tn)
          #pragma unroll
          for (int c=0;c<4;++c) C2[tm][tn][c]=0.0f;

      #pragma unroll 8
      for (int ks=0; ks<16; ++ks){
        const int ko = ks*16 + cK;
        u32 wb[2][2], wl0[2], wl1[2];
        #pragma unroll
        for (int tn=0; tn<2; ++tn){
          const half* p = w2s + (w*16 + tn*8 + rA)*S2 + ko;
          wb[tn][0] = lds32(p);
          wb[tn][1] = lds32(p + 8);
          const u32* q = g_w2l + ((w*2+tn)*16 + ks)*64;
          wl0[tn] = __ldg(q + lane);
          wl1[tn] = __ldg(q + 32 + lane);
        }
        #pragma unroll
        for (int tm=0; tm<3; ++tm){
          const half* pa = ah + (tm*16 + rA)*S2 + ko;
          u32 a0 = lds32(pa),          a1 = lds32(pa + 8*S2);
          u32 a2 = lds32(pa + 8),      a3 = lds32(pa + 8*S2 + 8);
          const half* pl = al + (tm*16 + rA)*S2 + ko;
          u32 l0 = lds32(pl),          l1 = lds32(pl + 8*S2);
          u32 l2 = lds32(pl + 8),      l3 = lds32(pl + 8*S2 + 8);
          #pragma unroll
          for (int tn=0; tn<2; ++tn){
            mma16816(C2[tm][tn], a0,a1,a2,a3, wb[tn][0], wb[tn][1]);
            mma16816(C2[tm][tn], l0,l1,l2,l3, wb[tn][0], wb[tn][1]);
            mma16816(C2[tm][tn], a0,a1,a2,a3, wl0[tn], wl1[tn]);
          }
        }
      }

      // ===== RK4(3/8) stage update (C2 cell (tm,tn,c): q = c>>1, p = c&1) =====
      #pragma unroll
      for (int tm=0; tm<3; ++tm)
        #pragma unroll
        for (int q=0; q<2; ++q){
          int r = tm*16 + q*8 + rA;
          #pragma unroll
          for (int tn=0; tn<2; ++tn){
            int d0 = w*16 + tn*8 + cK;
            float yn[2];
            #pragma unroll
            for (int p=0; p<2; ++p){
              int ix = tm*8 + q*4 + tn*2 + p;
              float kv = C2[tm][tn][q*2+p] + b2v[tn][p];
              if (st == 0){
                k1s[ix] = kv;
                yn[p] = fmaf(h*(1.0f/3.0f), kv, ys[ix]);
              } else if (st == 1){
                kAs[ix] = kv;
                yn[p] = fmaf(-h*(1.0f/3.0f), k1s[ix], fmaf(h, kv, ys[ix]));
              } else if (st == 2){
                yn[p] = fmaf(h, k1s[ix] - kAs[ix] + kv, ys[ix]);
                kAs[ix] = fmaf(3.0f, kAs[ix] + kv, k1s[ix]);   // k1 + 3(k2+k3)
              } else {
                yn[p] = fmaf(h*0.125f, kAs[ix] + kv, ys[ix]);
                ys[ix] = yn[p];
              }
            }
            half h0 = __float2half_rn(yn[0]), h1 = __float2half_rn(yn[1]);
            *(half2*)(yh + r*S1 + d0) = __halves2half2(h0, h1);
            *(half2*)(yl + r*S1 + d0) = __halves2half2(
                __float2half_rn(yn[0] - __half2float(h0)),
                __float2half_rn(yn[1] - __half2float(h1)));
            if (st == 3){
              int g = grow + r;
              *(float2*)(out + ((size_t)g*NT + step+1)*128 + d0) = make_float2(yn[0], yn[1]);
            }
          }
        }
      __syncthreads();
    }
  }
}

extern "C" void kernel_launch(void* const* d_in, const int* in_sizes, int n_in,
                              void* d_out, int out_size)
{
  const float* fp = (const float*)d_in[0];   // (3,2048,123)
  const float* ts = (const float*)d_in[1];   // (50)
  const float* W1 = (const float*)d_in[2];   // (256,128)
  const float* b1 = (const float*)d_in[3];   // (256)
  const float* W2 = (const float*)d_in[4];   // (128,256)
  const float* b2 = (const float*)d_in[5];   // (128)
  float* out = (float*)d_out;                // (3,2048,50,128)

  pack_lo<<<128, 256>>>(W1, W2);

  cudaFuncSetAttribute(ode_kernel,
                       cudaFuncAttributeMaxDynamicSharedMemorySize, SMEM_TOTAL);
  ode_kernel<<<NBLK, NTHR, SMEM_TOTAL>>>(fp, ts, W1, b1, W2, b2, out);
}

// round 17
// speedup vs baseline: 4.9190x; 1.0269x over previous
#include <cuda_runtime.h>
#include <cuda_fp16.h>
#include <math.h>

typedef unsigned int u32;

#define LAT 123
#define NT 50
#define NSTEP 49
#define NTHR 256
#define NBLK 128             // 128 CTAs x 48 rows = 6144, single wave

// smem halfs strides (padded: +8 halfs = 16B -> bank = 4*row+quad, conflict-free)
#define S1 136               // k=d dimension stride (128+8)
#define S2 264               // k=j dimension stride (256+8)

#define OFF_W1 0                         // w1s[j=256][S1]  (B of P1: n=j, k=d) fp16-hi
#define OFF_W2 69632                     // w2s[d=128][S2]  (B of P2: n=d, k=j) fp16-hi
#define OFF_YH 137216                    // yh[r=48][S1]
#define OFF_YL 150272                    // yl[r=48][S1]
#define OFF_AH 163328                    // ah[r=48][S2]
#define OFF_AL 188672                    // al[r=48][S2]
#define SMEM_TOTAL 214016                // <= 232448

// lo-weights, fragment-packed for coalesced LDG:
// P1 tile t = jtile*8 + ks (jtile 0..31, ks 0..7): u32[t*64 + reg*32 + lane]
// P2 tile t = dtile*16 + ks (dtile 0..15, ks 0..15)
__device__ u32 g_w1l[16384];
__device__ u32 g_w2l[16384];

__device__ __forceinline__ float tanh_hw(float x){
  float r; asm("tanh.approx.f32 %0, %1;" : "=f"(r) : "f"(x)); return r;
}
__device__ __forceinline__ void mma16816(float* c, u32 a0,u32 a1,u32 a2,u32 a3, u32 b0,u32 b1){
  asm volatile(
    "mma.sync.aligned.m16n8k16.row.col.f32.f16.f16.f32 "
    "{%0,%1,%2,%3},{%4,%5,%6,%7},{%8,%9},{%0,%1,%2,%3};"
    : "+f"(c[0]), "+f"(c[1]), "+f"(c[2]), "+f"(c[3])
    : "r"(a0), "r"(a1), "r"(a2), "r"(a3), "r"(b0), "r"(b1));
}
__device__ __forceinline__ u32 lds32(const half* p){ return *(const u32*)p; }

__device__ __forceinline__ half lo_h(float w){
  half hh = __float2half_rn(w);
  return __float2half_rn(w - __half2float(hh));
}

// pack W-lo residuals into B-fragment order
__global__ void pack_lo(const float* __restrict__ W1, const float* __restrict__ W2){
  int idx = blockIdx.x*256 + threadIdx.x;     // 0..32767
  if (idx < 16384){
    int t = idx >> 6, rem = idx & 63;
    int reg = rem >> 5, lane = rem & 31;
    int n = (t >> 3)*8 + (lane >> 2);               // j
    int k = (t & 7)*16 + (lane & 3)*2 + reg*8;      // d
    half h0 = lo_h(W1[n*128 + k]);
    half h1 = lo_h(W1[n*128 + k + 1]);
    half2 v = __halves2half2(h0, h1);
    g_w1l[idx] = *(u32*)&v;
  } else {
    int i2 = idx - 16384;
    int t = i2 >> 6, rem = i2 & 63;
    int reg = rem >> 5, lane = rem & 31;
    int n = (t >> 4)*8 + (lane >> 2);               // d
    int k = (t & 15)*16 + (lane & 3)*2 + reg*8;     // j
    half h0 = lo_h(W2[n*256 + k]);
    half h1 = lo_h(W2[n*256 + k + 1]);
    half2 v = __halves2half2(h0, h1);
    g_w2l[i2] = *(u32*)&v;
  }
}

__global__ __launch_bounds__(NTHR,1)
void ode_kernel(const float* __restrict__ fp, const float* __restrict__ ts,
                const float* __restrict__ W1, const float* __restrict__ b1,
                const float* __restrict__ W2, const float* __restrict__ b2,
                float* __restrict__ out)
{
  extern __shared__ char smem[];
  half* w1s = (half*)(smem + OFF_W1);
  half* w2s = (half*)(smem + OFF_W2);
  half* yh  = (half*)(smem + OFF_YH);
  half* yl  = (half*)(smem + OFF_YL);
  half* ah  = (half*)(smem + OFF_AH);
  half* al  = (half*)(smem + OFF_AL);

  const int tid  = threadIdx.x;
  const int lane = tid & 31;
  const int w    = tid >> 5;          // warp 0..7
  const int rA   = lane >> 2;         // fragment row (0..7)
  const int cK   = (lane & 3) * 2;    // fragment k-pair base

  // ---- load hi-weights into smem fp16 (one-time) ----
  for (int idx = tid; idx < 256*128; idx += NTHR){
    int j = idx >> 7, d = idx & 127;
    w1s[j*S1 + d] = __float2half_rn(W1[idx]);          // W1[j][d]
  }
  for (int idx = tid; idx < 128*256; idx += NTHR){
    int d = idx >> 8, j = idx & 255;
    w2s[d*S2 + j] = __float2half_rn(W2[idx]);          // W2[d][j]
  }

  // per-thread bias regs
  float b1v[4][2], b2v[2][2];
  #pragma unroll
  for (int tn=0; tn<4; ++tn){
    int j = w*32 + tn*8 + cK;
    b1v[tn][0] = __ldg(b1 + j);
    b1v[tn][1] = __ldg(b1 + j + 1);
  }
  #pragma unroll
  for (int tn=0; tn<2; ++tn){
    int d = w*16 + tn*8 + cK;
    b2v[tn][0] = __ldg(b2 + d);
    b2v[tn][1] = __ldg(b2 + d + 1);
  }

  const int grow = blockIdx.x * 48;

  // ---- RK4 cell ownership (matches P2 C layout): r = tm*16+q*8+rA, d = w*16+tn*8+cK+p
  float ys[24], k1s[24], kAs[24];
  #pragma unroll
  for (int tm=0; tm<3; ++tm)
    #pragma unroll
    for (int q=0; q<2; ++q){
      int r = tm*16 + q*8 + rA;
      int g = grow + r;
      #pragma unroll
      for (int tn=0; tn<2; ++tn){
        int d0 = w*16 + tn*8 + cK;
        float v0 = (d0   < LAT) ? __ldg(fp + (size_t)g*LAT + d0)   : 0.0f;
        float v1 = (d0+1 < LAT) ? __ldg(fp + (size_t)g*LAT + d0+1) : 0.0f;
        ys[tm*8+q*4+tn*2+0] = v0;
        ys[tm*8+q*4+tn*2+1] = v1;
        half h0 = __float2half_rn(v0), h1 = __float2half_rn(v1);
        *(half2*)(yh + r*S1 + d0) = __halves2half2(h0, h1);
        *(half2*)(yl + r*S1 + d0) = __halves2half2(
            __float2half_rn(v0 - __half2float(h0)),
            __float2half_rn(v1 - __half2float(h1)));
        *(float2*)(out + ((size_t)g*NT)*128 + d0) = make_float2(v0, v1);
      }
    }
  __syncthreads();

  #pragma unroll 1
  for (int step=0; step<NSTEP; ++step){
    const float t0 = __ldg(ts+step);
    const float h  = __ldg(ts+step+1) - t0;

    #pragma unroll 1
    for (int st=0; st<4; ++st){
      // ===== P1: C1[r, j] = yh*W1h + yl*W1h + yh*W1l ; warp j-slice [w*32, w*32+32) =====
      // pass-major MMA order: same accumulator re-touched at distance 12 (was 1)
      float C1[3][4][4];
      #pragma unroll
      for (int tm=0;tm<3;++tm)
        #pragma unroll
        for (int tn=0;tn<4;++tn)
          #pragma unroll
          for (int c=0;c<4;++c) C1[tm][tn][c]=0.0f;

      #pragma unroll
      for (int ks=0; ks<8; ++ks){
        const int ko = ks*16 + cK;
        u32 wb[4][2], wl0[4], wl1[4];
        #pragma unroll
        for (int tn=0; tn<4; ++tn){
          const half* p = w1s + (w*32 + tn*8 + rA)*S1 + ko;
          wb[tn][0] = lds32(p);
          wb[tn][1] = lds32(p + 8);
          const u32* q = g_w1l + ((w*4+tn)*8 + ks)*64;
          wl0[tn] = __ldg(q + lane);
          wl1[tn] = __ldg(q + 32 + lane);
        }
        u32 AH[3][4], AL[3][4];
        #pragma unroll
        for (int tm=0; tm<3; ++tm){
          const half* py = yh + (tm*16 + rA)*S1 + ko;
          AH[tm][0] = lds32(py);         AH[tm][1] = lds32(py + 8*S1);
          AH[tm][2] = lds32(py + 8);     AH[tm][3] = lds32(py + 8*S1 + 8);
          const half* pl = yl + (tm*16 + rA)*S1 + ko;
          AL[tm][0] = lds32(pl);         AL[tm][1] = lds32(pl + 8*S1);
          AL[tm][2] = lds32(pl + 8);     AL[tm][3] = lds32(pl + 8*S1 + 8);
        }
        #pragma unroll
        for (int tm=0; tm<3; ++tm)
          #pragma unroll
          for (int tn=0; tn<4; ++tn)
            mma16816(C1[tm][tn], AH[tm][0],AH[tm][1],AH[tm][2],AH[tm][3], wb[tn][0], wb[tn][1]);
        #pragma unroll
        for (int tm=0; tm<3; ++tm)
          #pragma unroll
          for (int tn=0; tn<4; ++tn)
            mma16816(C1[tm][tn], AL[tm][0],AL[tm][1],AL[tm][2],AL[tm][3], wb[tn][0], wb[tn][1]);
        #pragma unroll
        for (int tm=0; tm<3; ++tm)
          #pragma unroll
          for (int tn=0; tn<4; ++tn)
            mma16816(C1[tm][tn], AH[tm][0],AH[tm][1],AH[tm][2],AH[tm][3], wl0[tn], wl1[tn]);
      }

      // epilogue: act = tanh(C1 + b1), split hi/lo, store [r][j]
      #pragma unroll
      for (int tm=0; tm<3; ++tm)
        #pragma unroll
        for (int tn=0; tn<4; ++tn){
          int jb = w*32 + tn*8 + cK;
          float h0 = tanh_hw(C1[tm][tn][0] + b1v[tn][0]);
          float h1 = tanh_hw(C1[tm][tn][1] + b1v[tn][1]);
          float h2 = tanh_hw(C1[tm][tn][2] + b1v[tn][0]);
          float h3 = tanh_hw(C1[tm][tn][3] + b1v[tn][1]);
          half a0 = __float2half_rn(h0), a1 = __float2half_rn(h1);
          half a2 = __float2half_rn(h2), a3 = __float2half_rn(h3);
          int r0 = tm*16 + rA;
          *(half2*)(ah + r0*S2 + jb)       = __halves2half2(a0, a1);
          *(half2*)(ah + (r0+8)*S2 + jb)   = __halves2half2(a2, a3);
          *(half2*)(al + r0*S2 + jb)       = __halves2half2(
              __float2half_rn(h0 - __half2float(a0)),
              __float2half_rn(h1 - __half2float(a1)));
          *(half2*)(al + (r0+8)*S2 + jb)   = __halves2half2(
              __float2half_rn(h2 - __half2float(a2)),
              __float2half_rn(h3 - __half2float(a3)));
        }
      __syncthreads();

      // ===== P2: C2[r, d] = ah*W2h + al*W2h + ah*W2l ; warp d-slice [w*16, w*16+16) =====
      float C2[3][2][4];
      #pragma unroll
      for (int tm=0;tm<3;++tm)
        #pragma unroll
        for (int tn=0;tn<2;++tn)
          #pragma unroll
          for (int c=0;c<4;++c) C2[tm][tn][c]=0.0f;

      #pragma unroll 8
      for (int ks=0; ks<16; ++ks){
        const int ko = ks*16 + cK;
        u32 wb[2][2], wl0[2], wl1[2];
        #pragma unroll
        for (int tn=0; tn<2; ++tn){
          const half* p = w2s + (w*16 + tn*8 + rA)*S2 + ko;
          wb[tn][0] = lds32(p);
          wb[tn][1] = lds32(p + 8);
          const u32* q = g_w2l + ((w*2+tn)*16 + ks)*64;
          wl0[tn] = __ldg(q + lane);
          wl1[tn] = __ldg(q + 32 + lane);
        }
        u32 AH[3][4], AL[3][4];
        #pragma unroll
        for (int tm=0; tm<3; ++tm){
          const half* pa = ah + (tm*16 + rA)*S2 + ko;
          AH[tm][0] = lds32(pa);         AH[tm][1] = lds32(pa + 8*S2);
          AH[tm][2] = lds32(pa + 8);     AH[tm][3] = lds32(pa + 8*S2 + 8);
          const half* pl = al + (tm*16 + rA)*S2 + ko;
          AL[tm][0] = lds32(pl);         AL[tm][1] = lds32(pl + 8*S2);
          AL[tm][2] = lds32(pl + 8);     AL[tm][3] = lds32(pl + 8*S2 + 8);
        }
        #pragma unroll
        for (int tm=0; tm<3; ++tm)
          #pragma unroll
          for (int tn=0; tn<2; ++tn)
            mma16816(C2[tm][tn], AH[tm][0],AH[tm][1],AH[tm][2],AH[tm][3], wb[tn][0], wb[tn][1]);
        #pragma unroll
        for (int tm=0; tm<3; ++tm)
          #pragma unroll
          for (int tn=0; tn<2; ++tn)
            mma16816(C2[tm][tn], AL[tm][0],AL[tm][1],AL[tm][2],AL[tm][3], wb[tn][0], wb[tn][1]);
        #pragma unroll
        for (int tm=0; tm<3; ++tm)
          #pragma unroll
          for (int tn=0; tn<2; ++tn)
            mma16816(C2[tm][tn], AH[tm][0],AH[tm][1],AH[tm][2],AH[tm][3], wl0[tn], wl1[tn]);
      }

      // ===== RK4(3/8) stage update (C2 cell (tm,tn,c): q = c>>1, p = c&1) =====
      #pragma unroll
      for (int tm=0; tm<3; ++tm)
        #pragma unroll
        for (int q=0; q<2; ++q){
          int r = tm*16 + q*8 + rA;
          #pragma unroll
          for (int tn=0; tn<2; ++tn){
            int d0 = w*16 + tn*8 + cK;
            float yn[2];
            #pragma unroll
            for (int p=0; p<2; ++p){
              int ix = tm*8 + q*4 + tn*2 + p;
              float kv = C2[tm][tn][q*2+p] + b2v[tn][p];
              if (st == 0){
                k1s[ix] = kv;
                yn[p] = fmaf(h*(1.0f/3.0f), kv, ys[ix]);
              } else if (st == 1){
                kAs[ix] = kv;
                yn[p] = fmaf(-h*(1.0f/3.0f), k1s[ix], fmaf(h, kv, ys[ix]));
              } else if (st == 2){
                yn[p] = fmaf(h, k1s[ix] - kAs[ix] + kv, ys[ix]);
                kAs[ix] = fmaf(3.0f, kAs[ix] + kv, k1s[ix]);   // k1 + 3(k2+k3)
              } else {
                yn[p] = fmaf(h*0.125f, kAs[ix] + kv, ys[ix]);
                ys[ix] = yn[p];
              }
            }
            half h0 = __float2half_rn(yn[0]), h1 = __float2half_rn(yn[1]);
            *(half2*)(yh + r*S1 + d0) = __halves2half2(h0, h1);
            *(half2*)(yl + r*S1 + d0) = __halves2half2(
                __float2half_rn(yn[0] - __half2float(h0)),
                __float2half_rn(yn[1] - __half2float(h1)));
            if (st == 3){
              int g = grow + r;
              *(float2*)(out + ((size_t)g*NT + step+1)*128 + d0) = make_float2(yn[0], yn[1]);
            }
          }
        }
      __syncthreads();
    }
  }
}

extern "C" void kernel_launch(void* const* d_in, const int* in_sizes, int n_in,
                              void* d_out, int out_size)
{
  const float* fp = (const float*)d_in[0];   // (3,2048,123)
  const float* ts = (const float*)d_in[1];   // (50)
  const float* W1 = (const float*)d_in[2];   // (256,128)
  const float* b1 = (const float*)d_in[3];   // (256)
  const float* W2 = (const float*)d_in[4];   // (128,256)
  const float* b2 = (const float*)d_in[5];   // (128)
  float* out = (float*)d_out;                // (3,2048,50,128)

  pack_lo<<<128, 256>>>(W1, W2);

  cudaFuncSetAttribute(ode_kernel,
                       cudaFuncAttributeMaxDynamicSharedMemorySize, SMEM_TOTAL);
  ode_kernel<<<NBLK, NTHR, SMEM_TOTAL>>>(fp, ts, W1, b1, W2, b2, out);
}